// round 13
// baseline (speedup 1.0000x reference)
#include <cuda_runtime.h>

// Problem shape (fixed by setup_inputs):
//   x1: [B=32, C=64, h=42, w=42]       float32
//   x2: [B=32, S=25, C=64, h=42, w=42] float32
//   out: [B, S*h*w] = [32, 44100]      float32
// out[b, s*HW + p] = sqrt( sum_c (x1[b,c,p] - x2[b,s,c,p])^2 )
//
// Dedup + asymmetric-deep pipeline:
//   - 5 supports per thread: x1 loaded once per channel (LDG count -40%,
//     x1 L2 traffic /5) -> nearly every load slot targets DRAM (x2).
//   - x2 prefetch distance 2 over 1-channel stages -> 10-15 x2 loads
//     continuously in flight per thread.
//   - block=160, grid=441 -> 3 CTAs/SM, all CTAs resident in ONE wave.

#define B_   32
#define S_   25
#define C_   64
#define HW_  1764          // 42*42
#define HW4_ 441           // HW/4 (exact)

#define SG_  5             // supports per thread
#define NSG_ (S_ / SG_)    // 5 support-groups
#define TOTAL_ (B_ * NSG_ * HW4_)   // 70560 threads

#define PLANE4_ (C_ * HW4_)         // float4s per [C,h,w] slab = 28224

#define BLOCK_ 160
#define NBUF2_ 3           // x2 buffers (prefetch distance 2)

__global__ __launch_bounds__(BLOCK_, 3)
void euclidean_block_kernel(const float* __restrict__ x1,
                            const float* __restrict__ x2,
                            float* __restrict__ out) {
    int t = blockIdx.x * BLOCK_ + threadIdx.x;
    if (t >= TOTAL_) return;

    int p4   = t % HW4_;
    int rest = t / HW4_;
    int sg   = rest % NSG_;
    int b    = rest / NSG_;

    const float4* __restrict__ x1p =
        reinterpret_cast<const float4*>(x1) + (size_t)b * PLANE4_ + p4;
    const float4* __restrict__ x2p =
        reinterpret_cast<const float4*>(x2) +
        ((size_t)b * S_ + sg * SG_) * PLANE4_ + p4;

    float4 acc[SG_];
    #pragma unroll
    for (int j = 0; j < SG_; ++j) acc[j] = make_float4(0.f, 0.f, 0.f, 0.f);

    float4 v[NBUF2_][SG_];   // x2: deep (60 regs)
    float4 a[2];             // x1: distance 1 (8 regs)

    // Prologue: x2 channels 0,1 in flight; x1 channel 0 in flight.
    #pragma unroll
    for (int s = 0; s < NBUF2_ - 1; ++s) {
        #pragma unroll
        for (int j = 0; j < SG_; ++j)
            v[s][j] = __ldcs(&x2p[(size_t)j * PLANE4_ + s * HW4_]);
    }
    a[0] = x1p[0];

    #pragma unroll
    for (int c = 0; c < C_; ++c) {
        // Prefetch x2 channel c+2 (keeps 10-15 x2 loads outstanding).
        if (c + 2 < C_) {
            const int pf = (c + 2) % NBUF2_;
            #pragma unroll
            for (int j = 0; j < SG_; ++j)
                v[pf][j] = __ldcs(&x2p[(size_t)j * PLANE4_ + (c + 2) * HW4_]);
        }
        // Prefetch x1 channel c+1 (L2 hit; distance 1 suffices).
        if (c + 1 < C_) {
            a[(c + 1) & 1] = x1p[(c + 1) * HW4_];
        }

        // Consume channel c across all 5 supports.
        const float4 av = a[c & 1];
        const int cb = c % NBUF2_;
        #pragma unroll
        for (int j = 0; j < SG_; ++j) {
            float d0 = av.x - v[cb][j].x;
            float d1 = av.y - v[cb][j].y;
            float d2 = av.z - v[cb][j].z;
            float d3 = av.w - v[cb][j].w;
            acc[j].x = fmaf(d0, d0, acc[j].x);
            acc[j].y = fmaf(d1, d1, acc[j].y);
            acc[j].z = fmaf(d2, d2, acc[j].z);
            acc[j].w = fmaf(d3, d3, acc[j].w);
        }
    }

    // write 5 outputs: (b*25 + sg*5 + j)*441 + p4  (float4 units)
    float4* __restrict__ op =
        reinterpret_cast<float4*>(out) +
        ((size_t)b * S_ + sg * SG_) * HW4_ + p4;
    #pragma unroll
    for (int j = 0; j < SG_; ++j) {
        float4 r;
        r.x = sqrtf(acc[j].x);
        r.y = sqrtf(acc[j].y);
        r.z = sqrtf(acc[j].z);
        r.w = sqrtf(acc[j].w);
        op[(size_t)j * HW4_] = r;
    }
}

extern "C" void kernel_launch(void* const* d_in, const int* in_sizes, int n_in,
                              void* d_out, int out_size) {
    const float* x1 = (const float*)d_in[0];
    const float* x2 = (const float*)d_in[1];
    float* out = (float*)d_out;

    const int blocks = (TOTAL_ + BLOCK_ - 1) / BLOCK_;  // 441 -> single wave
    euclidean_block_kernel<<<blocks, BLOCK_>>>(x1, x2, out);
}

// round 14
// speedup vs baseline: 1.0345x; 1.0345x over previous
#include <cuda_runtime.h>

// Problem shape (fixed by setup_inputs):
//   x1: [B=32, C=64, h=42, w=42]       float32
//   x2: [B=32, S=25, C=64, h=42, w=42] float32
//   out: [B, S*h*w] = [32, 44100]      float32
// out[b, s*HW + p] = sqrt( sum_c (x1[b,c,p] - x2[b,s,c,p])^2 )
//
// FINAL (R10 champion): triple-buffered register pipeline, prefetch distance
// 2 over 4-channel stages -> each thread keeps 16 float4 loads continuously
// in flight. x2 -> __ldcs streaming; x1 -> caching loads (reused across the
// 25 supports via L1/L2); plain coalesced float4 stores. Flat 1379-CTA grid.
//
// Measured: 57.7us e2e, 82.2% DRAM-active, 6.51 TB/s with traffic at the
// 381 MB floor — the achievable HBM roofline for this access mix. All
// perturbations (deeper pipeline, asymmetric depth, x1 dedup, cache-hint
// changes, grid reshaping, persistent grid) measured neutral or worse.

#define B_  32
#define S_  25
#define C_  64
#define HW_ 1764          // 42*42
#define HW4_ 441          // HW/4 (exact)
#define TOTAL_ (B_ * S_ * HW4_)   // 352800 threads, one float4 output each

#define CB_ 4                      // channels per pipeline stage
#define NSTAGE_ (C_ / CB_)         // 16 stages
#define NBUF_ 3                    // prefetch distance 2

__global__ __launch_bounds__(256, 2)
void euclidean_block_kernel(const float* __restrict__ x1,
                            const float* __restrict__ x2,
                            float* __restrict__ out) {
    int t = blockIdx.x * blockDim.x + threadIdx.x;
    if (t >= TOTAL_) return;

    int p4 = t % HW4_;          // which float4 within the 1764-pixel plane
    int bs = t / HW4_;          // (b*S + s)
    int b  = bs / S_;

    const float4* __restrict__ x1p =
        reinterpret_cast<const float4*>(x1 + (size_t)b * C_ * HW_) + p4;
    const float4* __restrict__ x2p =
        reinterpret_cast<const float4*>(x2 + (size_t)bs * C_ * HW_) + p4;

    float ax = 0.f, ay = 0.f, az = 0.f, aw = 0.f;

    float4 a[NBUF_][CB_], v[NBUF_][CB_];

    // Prologue: stages 0 and 1 in flight before any consumption.
    #pragma unroll
    for (int s = 0; s < 2; ++s) {
        #pragma unroll
        for (int i = 0; i < CB_; ++i) {
            a[s][i] = x1p[(s * CB_ + i) * HW4_];
            v[s][i] = __ldcs(&x2p[(s * CB_ + i) * HW4_]);
        }
    }

    #pragma unroll
    for (int s = 0; s < NSTAGE_; ++s) {
        const int cur = s % NBUF_;

        // Prefetch stage s+2 -> keeps 16 loads outstanding at all times.
        if (s + 2 < NSTAGE_) {
            const int pf = (s + 2) % NBUF_;
            const int c0 = (s + 2) * CB_;
            #pragma unroll
            for (int i = 0; i < CB_; ++i) {
                a[pf][i] = x1p[(c0 + i) * HW4_];
                v[pf][i] = __ldcs(&x2p[(c0 + i) * HW4_]);
            }
        }

        // Consume stage s.
        #pragma unroll
        for (int i = 0; i < CB_; ++i) {
            float d0 = a[cur][i].x - v[cur][i].x;
            float d1 = a[cur][i].y - v[cur][i].y;
            float d2 = a[cur][i].z - v[cur][i].z;
            float d3 = a[cur][i].w - v[cur][i].w;
            ax = fmaf(d0, d0, ax);
            ay = fmaf(d1, d1, ay);
            az = fmaf(d2, d2, az);
            aw = fmaf(d3, d3, aw);
        }
    }

    float4 r;
    r.x = sqrtf(ax);
    r.y = sqrtf(ay);
    r.z = sqrtf(az);
    r.w = sqrtf(aw);

    reinterpret_cast<float4*>(out)[(size_t)bs * HW4_ + p4] = r;
}

extern "C" void kernel_launch(void* const* d_in, const int* in_sizes, int n_in,
                              void* d_out, int out_size) {
    const float* x1 = (const float*)d_in[0];
    const float* x2 = (const float*)d_in[1];
    float* out = (float*)d_out;

    const int threads = 256;
    const int blocks = (TOTAL_ + threads - 1) / threads;  // 1379, flat grid
    euclidean_block_kernel<<<blocks, threads>>>(x1, x2, out);
}